// round 8
// baseline (speedup 1.0000x reference)
#include <cuda_runtime.h>

#define T_STEPS 96
#define BATCH   128

// Output section offsets (floats), tuple order:
// mu_filt, sigma_filt, mu_pred, sigma_pred, latent_means, latent_variances, S
#define OFF_MUF   0
#define OFF_SIGF  393216
#define OFF_MUP   12976128
#define OFF_SIGP  13369344
#define OFF_LM    25952256
#define OFF_LV    26738688
#define OFF_S     51904512

#define PZ 36   // 32-wide rows padded: 144B, 16B-aligned
#define PA 20   // 16-wide rows padded: 80B, 16B-aligned

__device__ __forceinline__ float dot4(float4 a, float4 b) {
    return a.x * b.x + a.y * b.y + a.z * b.z + a.w * b.w;
}

__global__ __launch_bounds__(256, 1)
void kalman_kernel(const float* __restrict__ obs,
                   const float* __restrict__ Ag_all,
                   const float* __restrict__ Cg_all,
                   const float* __restrict__ Dg_all,
                   float* __restrict__ out)
{
    const int tid  = threadIdx.x;

    // ---------------- writer blocks: latent_variances (input-independent) ----
    if (blockIdx.x >= BATCH) {
        float* out_lv = out + OFF_LV;
        int wb = blockIdx.x - BATCH;          // 0..19
        for (int t = 0; t < T_STEPS; ++t) {
            float d0 = (t >= 2) ? 0.08f : 0.f;
            float d1 = (t <  4) ? 20.f  : 0.f;
            float4* dst = (float4*)(out_lv + (size_t)t * BATCH * 2048);
            for (int e4 = wb * 256 + tid; e4 < 65536; e4 += 20 * 256) {
                int v2 = (e4 * 4) & 2047;
                int l  = v2 >> 10;
                int ij = v2 & 1023;
                int i  = ij >> 5, j0 = ij & 31;
                float dv = l ? d1 : d0;
                bool hit = ((i >> 2) == (j0 >> 2));
                float4 v;
                v.x = (hit && (i & 3) == 0) ? dv : 0.f;
                v.y = (hit && (i & 3) == 1) ? dv : 0.f;
                v.z = (hit && (i & 3) == 2) ? dv : 0.f;
                v.w = (hit && (i & 3) == 3) ? dv : 0.f;
                dst[e4] = v;
            }
        }
        return;
    }

    const int b    = blockIdx.x;
    const int lane = tid & 31;
    const int wid  = tid >> 5;       // 0..7

    __shared__ __align__(16) float sigB[2][32][PZ]; // sigma ping-pong (symmetric)
    __shared__ __align__(16) float Ush [32][PZ];    // U = A @ sigma
    __shared__ __align__(16) float Rsh [32][PZ];    // 20*D@D^T (t<4)
    __shared__ __align__(16) float Am  [32][PZ];    // A[b,t+1,0]
    __shared__ __align__(16) float Dm  [32][PZ];    // D[b,t+1,0]
    __shared__ __align__(16) float Ct  [16][PZ];    // C[b,t]
    __shared__ __align__(16) float CSr [16][PZ];    // CS = C@sigma, row-major
    __shared__ __align__(16) float CSc [32][PA];    // W = sigma C^T (rows = z)
    __shared__ __align__(16) float Vsh [32][PA];    // V = A @ W
    __shared__ __align__(16) float Gsh [32][PA];    // G = V @ Sinv (warp-local rows)
    __shared__ __align__(16) float Ksh [32][PA];    // K = W @ Sinv (warp-local rows)
    __shared__ __align__(16) float Sinv[16][PA];
    __shared__ __align__(16) float Ssh [16][PA];
    __shared__ __align__(16) float muB[2][32];
    __shared__ __align__(16) float amv[32], dchv[32], rv[16], ov[16], svsh[16];
    __shared__ __align__(16) float chain[24][32];

    float* out_muf  = out + OFF_MUF;
    float* out_sigf = out + OFF_SIGF;
    float* out_mup  = out + OFF_MUP;
    float* out_sigp = out + OFF_SIGP;
    float* out_lm   = out + OFF_LM;
    float* out_S    = out + OFF_S;

    // ---------------- Prologue: top-level latent chain ----------------
    if (tid < 32) chain[0][tid] = 0.01f;
    {
        float4 pf[3];
        #pragma unroll
        for (int s = 0; s < 3; ++s) {
            const float* Ag = Ag_all + ((size_t)(b * T_STEPS + 4 * (s + 1)) * 3 + 2) * 1024;
            pf[s] = *(const float4*)(Ag + tid * 4);
        }
        __syncthreads();
        for (int j = 1; j <= 23; ++j) {
            int s = (j - 1) % 3;
            *(float4*)&Am[tid >> 3][(tid & 7) * 4] = pf[s];
            if (j + 3 <= 23) {
                const float* Ag = Ag_all + ((size_t)(b * T_STEPS + 4 * (j + 3)) * 3 + 2) * 1024;
                pf[s] = *(const float4*)(Ag + tid * 4);
            }
            __syncthreads();
            if (tid < 32) {
                const float4* ar = (const float4*)&Am[tid][0];
                const float4* ch = (const float4*)&chain[j - 1][0];
                float sm = 0.f;
                #pragma unroll
                for (int q = 0; q < 8; ++q) sm += dot4(ar[q], ch[q]);
                chain[j][tid] = sm;
            }
            __syncthreads();
        }
    }

    // ---------------- init state + t=0 prior outputs + step-0/1 operands ----
    float4 rA, rD, rC = make_float4(0, 0, 0, 0);
    float  rO = 0.f;
    {
        if (tid < 128)
            *(float4*)&Ct[tid >> 3][(tid & 7) * 4] =
                *(const float4*)(Cg_all + (size_t)(b * T_STEPS) * 512 + tid * 4);
        if (tid < 16) ov[tid] = obs[(size_t)b * 16 + tid];
        {
            int row = tid >> 3, c0 = (tid & 7) * 4;
            float4 sv = make_float4(0, 0, 0, 0);
            if (row >= c0 && row < c0 + 4) {
                int d = row - c0;
                sv.x = (d == 0) ? 20.f : 0.f;
                sv.y = (d == 1) ? 20.f : 0.f;
                sv.z = (d == 2) ? 20.f : 0.f;
                sv.w = (d == 3) ? 20.f : 0.f;
            }
            *(float4*)&sigB[0][row][c0] = sv;
            *(float4*)(out_sigp + (size_t)b * 1024 + tid * 4) = sv;
        }
        if (tid < 32) muB[0][tid] = 0.f;
        if (tid < 8)
            *(float4*)(out_mup + (size_t)b * 32 + tid * 4) = make_float4(0, 0, 0, 0);
        rA = *(const float4*)(Ag_all + (size_t)(b * T_STEPS + 1) * 3 * 1024 + tid * 4);
        rD = *(const float4*)(Dg_all + (size_t)(b * T_STEPS + 1) * 2 * 1024 + tid * 4);
    }
    __syncthreads();

    // ---------------- main sequential filter ----------------
    for (int t = 0; t < T_STEPS; ++t) {
        const size_t tb = (size_t)t * BATCH + b;
        float (*sgc)[PZ] = sigB[t & 1];
        float (*sgn)[PZ] = sigB[(t + 1) & 1];
        float* muc = muB[t & 1];
        float* mun = muB[(t + 1) & 1];
        const bool more = (t + 1 < T_STEPS);

        float4 scol[8];   // register-cached sigma column `lane` (reused in P3)

        // ---- P1: STS A/D[t+1]; prefetch; CS = C@sigma; r = o - C@mu ----
        {
            int ar2 = tid >> 3, ac = (tid & 7) * 4;
            *(float4*)&Am[ar2][ac] = rA;
            *(float4*)&Dm[ar2][ac] = rD;
            if (t + 2 < T_STEPS) {
                rA = *(const float4*)(Ag_all + (size_t)(b * T_STEPS + t + 2) * 3 * 1024 + tid * 4);
                rD = *(const float4*)(Dg_all + (size_t)(b * T_STEPS + t + 2) * 2 * 1024 + tid * 4);
            }
            if (more) {
                if (tid < 128)
                    rC = *(const float4*)(Cg_all + (size_t)(b * T_STEPS + t + 1) * 512 + tid * 4);
                if (tid < 16)
                    rO = obs[(size_t)((t + 1) * BATCH + b) * 16 + tid];
            }
            const float4* sc = (const float4*)&sgc[lane][0];
            const float4* c0 = (const float4*)&Ct[wid][0];
            const float4* c1 = (const float4*)&Ct[wid + 8][0];
            float s0 = 0.f, s1 = 0.f;
            #pragma unroll
            for (int q = 0; q < 8; ++q) {
                float4 g = sc[q];
                scol[q] = g;
                s0 += dot4(c0[q], g);
                s1 += dot4(c1[q], g);
            }
            CSr[wid][lane] = s0;      CSr[wid + 8][lane] = s1;
            CSc[lane][wid] = s0;      CSc[lane][wid + 8] = s1;
            if (tid < 16) {
                const float4* c4 = (const float4*)&Ct[tid][0];
                const float4* m4 = (const float4*)muc;
                float rr = ov[tid];
                #pragma unroll
                for (int q = 0; q < 8; ++q) rr -= dot4(c4[q], m4[q]);
                rv[tid] = rr;
            }
        }
        __syncthreads();

        // ---- P2: S = CS@C^T + 0.03 I; write S out ----
        {
            int i = tid >> 4, j = tid & 15;
            const float4* a4 = (const float4*)&CSr[i][0];
            const float4* c4 = (const float4*)&Ct[j][0];
            float s = (i == j) ? 0.03f : 0.f;
            #pragma unroll
            for (int q = 0; q < 8; ++q) s += dot4(a4[q], c4[q]);
            Ssh[i][j] = s;
            out_S[tb * 256 + tid] = s;
        }
        __syncthreads();

        // ---- P3: warp0 GJ inverse; warps 1-7: U, V, Amu, Dch, R20, lm ----
        if (wid == 0) {
            const int lrow = lane & 15;
            float M[16];
            const float4* sr = (const float4*)&Ssh[lrow][0];
            #pragma unroll
            for (int q = 0; q < 4; ++q) {
                float4 v = sr[q];
                M[4 * q + 0] = v.x; M[4 * q + 1] = v.y;
                M[4 * q + 2] = v.z; M[4 * q + 3] = v.w;
            }
            #pragma unroll
            for (int j = 0; j < 16; ++j) {
                float pj = __shfl_sync(0xffffffffu, M[j], j);
                float ip;
                asm("rcp.approx.ftz.f32 %0, %1;" : "=f"(ip) : "f"(pj));
                float f  = M[j];
                bool isj = (lrow == j);
                #pragma unroll
                for (int kk = 1; kk < 16; ++kk) {
                    int k = (j + kk) & 15;     // k = j+1 first: shortens pivot chain
                    float rj = __shfl_sync(0xffffffffu, M[k], j);
                    float v  = rj * ip;
                    M[k] = isj ? v : fmaf(-f, v, M[k]);
                }
                M[j] = isj ? ip : (-f * ip);
            }
            if (lane < 16) {
                float4* dst = (float4*)&Sinv[lane][0];
                #pragma unroll
                for (int q = 0; q < 4; ++q)
                    dst[q] = make_float4(M[4 * q], M[4 * q + 1], M[4 * q + 2], M[4 * q + 3]);
            }
        } else {
            int ww   = wid - 1;     // 0..6
            int wtid = tid - 32;    // 0..223
            if (wtid < 16) {
                float4 v = make_float4(0, 0, 0, 0);
                if (wtid >= 8) v = *(const float4*)&chain[t >> 2][(wtid - 8) * 4];
                *(float4*)(out_lm + tb * 64 + wtid * 4) = v;
            }
            if (more) {
                // U = A @ sigma (rows ww + 7m), V = A @ W
                float4 wr[8];
                #pragma unroll
                for (int q = 0; q < 8; ++q) wr[q] = ((const float4*)&CSr[lane & 15][0])[q];
                #pragma unroll
                for (int m = 0; m < 5; ++m) {
                    int r = ww + 7 * m;
                    if (r < 32) {
                        const float4* ar = (const float4*)&Am[r][0];
                        float u = 0.f, v = 0.f;
                        #pragma unroll
                        for (int q = 0; q < 8; ++q) {
                            float4 a = ar[q];
                            u += dot4(a, scol[q]);
                            v += dot4(a, wr[q]);
                        }
                        Ush[r][lane] = u;
                        Vsh[r][lane & 15] = v;
                    }
                }
                if (ww == 6) {   // Amu + Dch (warp 7, lightest U load)
                    const float4* al7 = (const float4*)&Am[lane][0];
                    const float4* dl7 = (const float4*)&Dm[lane][0];
                    const float4* m4  = (const float4*)muc;
                    const float4* ch  = (const float4*)&chain[t >> 2][0];
                    float am = 0.f, dc = 0.f;
                    #pragma unroll
                    for (int q = 0; q < 8; ++q) {
                        am += dot4(al7[q], m4[q]);
                        dc += dot4(dl7[q], ch[q]);
                    }
                    amv[lane]  = am;
                    dchv[lane] = dc;
                }
                if (t < 4) {     // R20 = 20 * D @ D^T
                    float4 dcol[8];
                    #pragma unroll
                    for (int q = 0; q < 8; ++q) dcol[q] = ((const float4*)&Dm[lane][0])[q];
                    #pragma unroll
                    for (int m = 0; m < 5; ++m) {
                        int r = ww + 7 * m;
                        if (r < 32) {
                            const float4* dr = (const float4*)&Dm[r][0];
                            float s = 0.f;
                            #pragma unroll
                            for (int q = 0; q < 8; ++q) s += dot4(dr[q], dcol[q]);
                            Rsh[r][lane] = 20.f * s;
                        }
                    }
                }
            }
        }
        __syncthreads();

        // ---- P4 (merged, warp-local): K/G rows {w,w+8,w+16,w+24}; sv;
        //      sigf; mu_filt; sigma' = UA^T - GV^T + Q; mu'; stores ----
        {
            // next-step C/obs (Ct is dead after P2)
            if (more) {
                if (tid < 128) *(float4*)&Ct[tid >> 3][(tid & 7) * 4] = rC;
                if (tid < 16)  ov[tid] = rO;
            }
            float4 wl[4];
            #pragma unroll
            for (int q = 0; q < 4; ++q) wl[q] = ((const float4*)&CSc[lane][0])[q];

            // K[r][c] (+ G[r][c]) for this warp's rows, 2 elements/thread
            #pragma unroll
            for (int p = 0; p < 2; ++p) {
                int r = wid + 8 * (2 * p + (lane >> 4));
                int c = lane & 15;
                const float4* wr4 = (const float4*)&CSc[r][0];
                const float4* si  = (const float4*)&Sinv[c][0];
                float kv = 0.f;
                #pragma unroll
                for (int q = 0; q < 4; ++q) kv += dot4(wr4[q], si[q]);
                Ksh[r][c] = kv;
                if (more) {
                    const float4* vr4 = (const float4*)&Vsh[r][0];
                    float gv = 0.f;
                    #pragma unroll
                    for (int q = 0; q < 4; ++q) gv += dot4(vr4[q], si[q]);
                    Gsh[r][c] = gv;
                }
            }
            if (wid == 1 && lane < 16) {   // sv = Sinv @ r
                const float4* si = (const float4*)&Sinv[lane][0];
                const float4* r4 = (const float4*)rv;
                float s = 0.f;
                #pragma unroll
                for (int q = 0; q < 4; ++q) s += dot4(si[q], r4[q]);
                svsh[lane] = s;
            }
            float4 vl[4], al[8];
            if (more) {
                #pragma unroll
                for (int q = 0; q < 4; ++q) vl[q] = ((const float4*)&Vsh[lane][0])[q];
                #pragma unroll
                for (int q = 0; q < 8; ++q) al[q] = ((const float4*)&Am[lane][0])[q];
            }
            __syncwarp();

            // sigf rows: z = sigma - K W^T
            #pragma unroll
            for (int ii = 0; ii < 4; ++ii) {
                int i = wid + 8 * ii;
                const float4* kr = (const float4*)&Ksh[i][0];
                float z = sgc[i][lane];
                #pragma unroll
                for (int q = 0; q < 4; ++q) z -= dot4(kr[q], wl[q]);
                out_sigf[tb * 1024 + i * 32 + lane] = z;
            }
            if (wid == 1) {   // mu_filt = mu + W sv ; mu' = Amu + V sv + Dch
                const float4* sv4 = (const float4*)svsh;
                float4 s0 = sv4[0], s1 = sv4[1], s2 = sv4[2], s3 = sv4[3];
                float mz = muc[lane];
                mz += dot4(wl[0], s0) + dot4(wl[1], s1)
                    + dot4(wl[2], s2) + dot4(wl[3], s3);
                out_muf[tb * 32 + lane] = mz;
                if (more) {
                    float m = amv[lane] + dchv[lane];
                    m += dot4(vl[0], s0) + dot4(vl[1], s1)
                       + dot4(vl[2], s2) + dot4(vl[3], s3);
                    mun[lane] = m;
                    out_mup[(tb + BATCH) * 32 + lane] = m;
                }
            }
            if (more) {
                const size_t tb2 = tb + BATCH;
                #pragma unroll
                for (int ii = 0; ii < 4; ++ii) {
                    int i = wid + 8 * ii;
                    const float4* ur = (const float4*)&Ush[i][0];
                    const float4* gr = (const float4*)&Gsh[i][0];
                    float s = 0.f;
                    #pragma unroll
                    for (int q = 0; q < 8; ++q) s += dot4(ur[q], al[q]);
                    #pragma unroll
                    for (int q = 0; q < 4; ++q) s -= dot4(gr[q], vl[q]);
                    if (i == lane) s += 0.08f;
                    if (t < 4)     s += Rsh[i][lane];
                    sgn[i][lane] = s;
                    out_sigp[tb2 * 1024 + i * 32 + lane] = s;
                }
            }
        }
        __syncthreads();
    }
}

extern "C" void kernel_launch(void* const* d_in, const int* in_sizes, int n_in,
                              void* d_out, int out_size) {
    const float* obs = (const float*)d_in[0];
    const float* A   = (const float*)d_in[1];
    const float* C   = (const float*)d_in[2];
    const float* D   = (const float*)d_in[3];
    kalman_kernel<<<BATCH + 20, 256>>>(obs, A, C, D, (float*)d_out);
}